// round 15
// baseline (speedup 1.0000x reference)
#include <cuda_runtime.h>
#include <cuda_bf16.h>
#include <cstdint>
#include <cstddef>

#define Bc  2
#define Cc  256
#define Nn  32768
#define Dd  4
#define Hh  256
#define Ww  256
#define HWc 65536
#define NGc 3

// ---------------- device scratch (static, no allocs) ----------------
__device__ __nv_bfloat16 g_gridA[(size_t)Bc * HWc * Cc];   // 67 MB bf16 (atomic target; L2-resident)
__device__ __nv_bfloat16 g_gridB[(size_t)Bc * HWc * Cc];   // 67 MB bf16 (conv output)
__device__ float g_counts[Bc * NGc * HWc];
__device__ float g_weight[Bc * NGc * Nn];
__device__ float g_aff[2 * Cc];                    // a[c], bv[c]
__device__ float g_stats[2 * Cc];                  // sum / sumsq accumulators
__device__ __nv_bfloat16 g_w1f[Cc * Cc];
__device__ __nv_bfloat16 g_w2b[Dd * Cc * Cc];
__device__ float g_b1f[Cc];

// ---------------- counts / weights ----------------
__global__ void count_kernel(const int* __restrict__ cell, const float* __restrict__ occ,
                             float* __restrict__ counts) {
    int i = blockIdx.x * 256 + threadIdx.x;
    int n = i % Nn;
    int bg = i / Nn;
    int b = bg / NGc;
    atomicAdd(&counts[(size_t)bg * HWc + cell[i]], occ[(size_t)b * Nn + n]);
}

__global__ void weight_kernel(const int* __restrict__ cell, const float* __restrict__ occ,
                              const float* __restrict__ counts, float* __restrict__ w) {
    int i = blockIdx.x * 256 + threadIdx.x;
    int n = i % Nn;
    int bg = i / Nn;
    int b = bg / NGc;
    float o = occ[(size_t)b * Nn + n];
    float cnt = counts[(size_t)bg * HWc + cell[i]] * o;
    w[i] = o / (cnt + 1e-6f);
}

// ------- BN stats: per-(c, b, quarter) partial sums -> global atomics -------
#define SCHUNK (Nn / 4)
__global__ void stats_kernel(const float* __restrict__ tok, float* __restrict__ stats) {
    int c = blockIdx.x;
    int bq = blockIdx.y;            // b * 4 + quarter
    int b = bq >> 2, qt = bq & 3;
    int t = threadIdx.x;
    float s = 0.f, s2 = 0.f;
    const float4* p = (const float4*)(tok + ((size_t)b * Cc + c) * Nn + qt * SCHUNK);
#pragma unroll 4
    for (int i = t; i < SCHUNK / 4; i += 256) {
        float4 v = p[i];
        s  += v.x + v.y + v.z + v.w;
        s2 += v.x * v.x + v.y * v.y + v.z * v.z + v.w * v.w;
    }
    __shared__ float sh0[256], sh1[256];
    sh0[t] = s; sh1[t] = s2;
    __syncthreads();
    for (int o = 128; o > 0; o >>= 1) {
        if (t < o) { sh0[t] += sh0[t + o]; sh1[t] += sh1[t + o]; }
        __syncthreads();
    }
    if (t == 0) {
        atomicAdd(&stats[c], sh0[0]);
        atomicAdd(&stats[Cc + c], sh1[0]);
    }
}

// ---------------- stats -> affine (and re-zero stats) ----------------
__global__ void aff_kernel(float* __restrict__ stats, const float* __restrict__ gamma,
                           const float* __restrict__ beta, float* __restrict__ aff) {
    int c = threadIdx.x;
    const float inv = 1.0f / (float)(Bc * Nn);
    float m = stats[c] * inv;
    float v = stats[Cc + c] * inv - m * m;
    float a = gamma[c] * rsqrtf(v + 1e-5f);
    aff[c] = a;
    aff[Cc + c] = beta[c] - m * a;
    stats[c] = 0.f;
    stats[Cc + c] = 0.f;
}

// --- scatter (BN folded inline): proven 32x32 shape, paired bf16x2 atomics ---
__global__ void scatter_kernel(const float* __restrict__ tok, const int* __restrict__ cell_ind,
                               int g, const float* __restrict__ wgt, const float* __restrict__ aff,
                               __nv_bfloat16* __restrict__ grid) {
    int tx = threadIdx.x, ty = threadIdx.y;
    int n0 = blockIdx.x * 32, c0 = blockIdx.y * 32, b = blockIdx.z;
    __shared__ float s[32][33];
    __shared__ int   cs[32];
    __shared__ float ws[32];
    s[ty][tx] = tok[((size_t)b * Cc + c0 + ty) * Nn + n0 + tx];
    if (ty == 0) {
        cs[tx] = cell_ind[((size_t)b * NGc + g) * Nn + n0 + tx];
        ws[tx] = wgt[((size_t)b * NGc + g) * Nn + n0 + tx];
    }
    __syncthreads();
    int c = c0 + tx;
    float a = aff[c], bv = aff[Cc + c];
    float r = fmaf(a, s[tx][ty], bv);
    float contrib = ws[ty] * r;                    // channel c0+tx, point n0+ty
    // pair channels (2tx, 2tx+1); lanes tx<16 emit one bf16x2 atomic each
    float q0 = __shfl_sync(0xffffffffu, contrib, (2 * tx)     & 31);
    float q1 = __shfl_sync(0xffffffffu, contrib, (2 * tx + 1) & 31);
    if (tx < 16) {
        __nv_bfloat162 pk = __floats2bfloat162_rn(q0, q1);
        atomicAdd((__nv_bfloat162*)(grid + ((size_t)b * HWc + cs[ty]) * Cc + c0 + 2 * tx), pk);
    }
}

// -------- fused depthwise 3x3 conv x2 (relu between), NHWC bf16 in/out ----
// y-tile: 8 output rows per block (12 input rows, 10 conv1 rows) -> 1.5x y-overread
__global__ void dwconv2_kernel(const __nv_bfloat16* __restrict__ in, const float* __restrict__ kk1,
                               const float* __restrict__ kb1, const float* __restrict__ kk2,
                               const float* __restrict__ kb2, __nv_bfloat16* __restrict__ out) {
    int c  = threadIdx.x;
    int y0 = blockIdx.x * 8;
    int x0 = blockIdx.y * 64;
    int b  = blockIdx.z;
    float ka[9], kb[9];
#pragma unroll
    for (int i = 0; i < 9; i++) { ka[i] = kk1[c * 9 + i]; kb[i] = kk2[c * 9 + i]; }
    float b1 = kb1[c], b2 = kb2[c];
    const __nv_bfloat16* base = in  + (size_t)b * HWc * Cc + c;
    __nv_bfloat16* obase      = out + (size_t)b * HWc * Cc + c;

    bool rin[12];
    size_t rofi[12];
#pragma unroll
    for (int r = 0; r < 12; r++) {
        int yr = y0 - 2 + r;
        rin[r] = (yr >= 0 && yr < Hh);
        rofi[r] = (size_t)(rin[r] ? yr : 0) * Ww * Cc;
    }
    bool rc1[10];
#pragma unroll
    for (int r = 0; r < 10; r++) {
        int yc = y0 - 1 + r;
        rc1[r] = (yc >= 0 && yc < Hh);
    }

    float i0[12], i1[12], i2[12], c10[10], c11[10], c12[10];
#pragma unroll
    for (int r = 0; r < 10; r++) { c10[r] = 0.f; c11[r] = 0.f; }

    {
        int x = x0 - 2;
        bool ok = (x >= 0 && x < Ww);
        size_t xi = (size_t)(ok ? x : 0) * Cc;
#pragma unroll
        for (int r = 0; r < 12; r++)
            i0[r] = (ok && rin[r]) ? __bfloat162float(base[rofi[r] + xi]) : 0.f;
    }
    {
        int x = x0 - 1;
        bool ok = (x >= 0 && x < Ww);
        size_t xi = (size_t)(ok ? x : 0) * Cc;
#pragma unroll
        for (int r = 0; r < 12; r++)
            i1[r] = (ok && rin[r]) ? __bfloat162float(base[rofi[r] + xi]) : 0.f;
    }

    for (int xc = x0 - 1; xc <= x0 + 64; xc++) {
        {
            int x = xc + 1;
            bool ok = (x >= 0 && x < Ww);
            size_t xi = (size_t)(ok ? x : 0) * Cc;
#pragma unroll
            for (int r = 0; r < 12; r++)
                i2[r] = (ok && rin[r]) ? __bfloat162float(base[rofi[r] + xi]) : 0.f;
        }
        bool xok = (xc >= 0 && xc < Ww);
#pragma unroll
        for (int r = 0; r < 10; r++) {
            float a = b1;
            a = fmaf(ka[0], i0[r],     a);
            a = fmaf(ka[1], i1[r],     a);
            a = fmaf(ka[2], i2[r],     a);
            a = fmaf(ka[3], i0[r + 1], a);
            a = fmaf(ka[4], i1[r + 1], a);
            a = fmaf(ka[5], i2[r + 1], a);
            a = fmaf(ka[6], i0[r + 2], a);
            a = fmaf(ka[7], i1[r + 2], a);
            a = fmaf(ka[8], i2[r + 2], a);
            c12[r] = (xok && rc1[r]) ? fmaxf(a, 0.f) : 0.f;
        }
        if (xc >= x0 + 1) {
            int xo = xc - 1;
#pragma unroll
            for (int o = 0; o < 8; o++) {
                float a = b2;
                a = fmaf(kb[0], c10[o],     a);
                a = fmaf(kb[1], c11[o],     a);
                a = fmaf(kb[2], c12[o],     a);
                a = fmaf(kb[3], c10[o + 1], a);
                a = fmaf(kb[4], c11[o + 1], a);
                a = fmaf(kb[5], c12[o + 1], a);
                a = fmaf(kb[6], c10[o + 2], a);
                a = fmaf(kb[7], c11[o + 2], a);
                a = fmaf(kb[8], c12[o + 2], a);
                obase[((size_t)(y0 + o) * Ww + xo) * Cc] = __float2bfloat16(a);
            }
        }
#pragma unroll
        for (int r = 0; r < 12; r++) { i0[r] = i1[r]; i1[r] = i2[r]; }
#pragma unroll
        for (int r = 0; r < 10; r++) { c10[r] = c11[r]; c11[r] = c12[r]; }
    }
}

// ---------------- gather + residual ----------------
__global__ void gather_kernel(const __nv_bfloat16* __restrict__ grid,
                              const int* __restrict__ cell_ind, int g,
                              const float* __restrict__ occ, const float* __restrict__ scale,
                              float* __restrict__ tok) {
    int tx = threadIdx.x, ty = threadIdx.y;
    int n0 = blockIdx.x * 32, c0 = blockIdx.y * 32, b = blockIdx.z;
    __shared__ float s[32][33];
    __shared__ int   cs[32];
    __shared__ float os[32];
    if (ty == 0) {
        cs[tx] = cell_ind[((size_t)b * NGc + g) * Nn + n0 + tx];
        os[tx] = occ[(size_t)b * Nn + n0 + tx];
    }
    __syncthreads();
    float v = __bfloat162float(grid[((size_t)b * HWc + cs[ty]) * Cc + c0 + tx]) * os[ty];
    s[tx][ty] = v;
    __syncthreads();
    size_t o = ((size_t)b * Cc + c0 + ty) * Nn + n0 + tx;
    tok[o] = fmaf(scale[c0 + ty], s[ty][tx], tok[o]);
}

// ---------------- fold BN affine into W1 (output bf16) ----------------
__global__ void fold_kernel(const float* __restrict__ w1, const float* __restrict__ b1,
                            const float* __restrict__ aff, __nv_bfloat16* __restrict__ w1f,
                            float* __restrict__ b1f) {
    int o = blockIdx.x, t = threadIdx.x;
    float wv = w1[(size_t)o * Cc + t];
    w1f[(size_t)o * Cc + t] = __float2bfloat16(wv * aff[t]);
    float p = wv * aff[Cc + t];
    __shared__ float sh[256];
    sh[t] = p;
    __syncthreads();
    for (int s = 128; s > 0; s >>= 1) {
        if (t < s) sh[t] += sh[t + s];
        __syncthreads();
    }
    if (t == 0) b1f[o] = b1[o] + sh[0];
}

__global__ void cvt_bf16_kernel(const float* __restrict__ src, __nv_bfloat16* __restrict__ dst) {
    int i = blockIdx.x * 256 + threadIdx.x;
    dst[i] = __float2bfloat16(src[i]);
}

// ------- tensor-core fused double GEMM + residual: whole-W smem residency -------
#define GNT 128
#define XPAD 136   // 128 + 8 bf16 pad
#define WPAD 264   // 256 + 8 bf16 pad

__device__ __forceinline__ uint32_t smem_u32(const void* p) {
    return (uint32_t)__cvta_generic_to_shared(p);
}

#define MMA16816(ac, A, B)                                                        \
    asm volatile("mma.sync.aligned.m16n8k16.row.col.f32.bf16.bf16.f32 "           \
                 "{%0,%1,%2,%3},{%4,%5,%6,%7},{%8,%9},{%0,%1,%2,%3};"             \
                 : "+f"(ac[0]), "+f"(ac[1]), "+f"(ac[2]), "+f"(ac[3])             \
                 : "r"(A[0]), "r"(A[1]), "r"(A[2]), "r"(A[3]), "r"(B[0]), "r"(B[1]))

__device__ __forceinline__ void stage_w(const __nv_bfloat16* __restrict__ W,
                                        __nv_bfloat16* __restrict__ Ws, int tid) {
#pragma unroll
    for (int it = 0; it < 16; it++) {
        int f = it * 512 + tid;
        int row = f >> 5;
        int col8 = (f & 31) << 3;
        uint4 v = *(const uint4*)(W + (size_t)row * 256 + col8);
        *(uint4*)(Ws + row * WPAD + col8) = v;
    }
}

__device__ __forceinline__ void mm_tc(const __nv_bfloat16* __restrict__ Ws,
                                      const __nv_bfloat16* __restrict__ Bsm,
                                      float (&acc)[4][4][4], int lane, int m0, int nb) {
#pragma unroll
    for (int i = 0; i < 4; i++)
#pragma unroll
        for (int j = 0; j < 4; j++)
#pragma unroll
            for (int q = 0; q < 4; q++) acc[i][j][q] = 0.f;

#pragma unroll
    for (int ks = 0; ks < 16; ks++) {
        int k0 = ks * 16;
        uint32_t a[4][4];
#pragma unroll
        for (int i = 0; i < 4; i++) {
            const __nv_bfloat16* p =
                Ws + (m0 + 16 * i + (lane & 15)) * WPAD + k0 + ((lane >> 4) << 3);
            asm volatile("ldmatrix.sync.aligned.m8n8.x4.shared.b16 {%0,%1,%2,%3}, [%4];"
                         : "=r"(a[i][0]), "=r"(a[i][1]), "=r"(a[i][2]), "=r"(a[i][3])
                         : "r"(smem_u32(p)));
        }
        uint32_t bf[4][2];
#pragma unroll
        for (int jj = 0; jj < 2; jj++) {
            const __nv_bfloat16* q =
                Bsm + (k0 + (lane & 15)) * XPAD + nb + 16 * jj + ((lane >> 4) << 3);
            asm volatile("ldmatrix.sync.aligned.m8n8.x4.trans.shared.b16 {%0,%1,%2,%3}, [%4];"
                         : "=r"(bf[2 * jj][0]), "=r"(bf[2 * jj][1]),
                           "=r"(bf[2 * jj + 1][0]), "=r"(bf[2 * jj + 1][1])
                         : "r"(smem_u32(q)));
        }
#pragma unroll
        for (int i = 0; i < 4; i++)
#pragma unroll
            for (int j = 0; j < 4; j++) MMA16816(acc[i][j], a[i], bf[j]);
    }
}

__global__ void __launch_bounds__(512, 1)
gemm_tc_kernel(float* __restrict__ tok, const __nv_bfloat16* __restrict__ w1f,
               const float* __restrict__ b1f, const __nv_bfloat16* __restrict__ w2,
               const float* __restrict__ b2, const float* __restrict__ scale) {
    extern __shared__ __nv_bfloat16 sm[];
    __nv_bfloat16* Ws = sm;                       // 256 * 264
    __nv_bfloat16* Xs = sm + 256 * WPAD;          // 256 * 136 — also h1
    int tid = threadIdx.x;
    int b   = blockIdx.x >> 8;
    int n0  = (blockIdx.x & 255) << 7;

    stage_w(w1f, Ws, tid);
    const float* tb = tok + (size_t)b * Cc * Nn;
#pragma unroll
    for (int i = 0; i < 16; i++) {
        int idx = i * 512 + tid;
        int row = idx >> 5;
        int c4  = idx & 31;
        float4 v = *(const float4*)(tb + (size_t)row * Nn + n0 + c4 * 4);
        __nv_bfloat162 p0 = __floats2bfloat162_rn(v.x, v.y);
        __nv_bfloat162 p1 = __floats2bfloat162_rn(v.z, v.w);
        uint2 pk;
        pk.x = *(uint32_t*)&p0;
        pk.y = *(uint32_t*)&p1;
        *(uint2*)(Xs + row * XPAD + c4 * 4) = pk;
    }
    __syncthreads();

    int lane = tid & 31, warp = tid >> 5;
    int m0 = (warp >> 2) * 64;
    int nb = (warp & 3) * 32;
    int r0 = m0 + (lane >> 2);
    int cb = nb + 2 * (lane & 3);

    float acc[4][4][4];

    // ---- GEMM1: h1 = relu(W1f @ x + b1f) ----
    mm_tc(Ws, Xs, acc, lane, m0, nb);
    __syncthreads();
#pragma unroll
    for (int i = 0; i < 4; i++) {
        int r = r0 + 16 * i;
        float bia = __ldg(b1f + r);
        float bib = __ldg(b1f + r + 8);
#pragma unroll
        for (int j = 0; j < 4; j++) {
            int cc = cb + 8 * j;
            __nv_bfloat162 h0 = __floats2bfloat162_rn(fmaxf(acc[i][j][0] + bia, 0.f),
                                                      fmaxf(acc[i][j][1] + bia, 0.f));
            __nv_bfloat162 h1 = __floats2bfloat162_rn(fmaxf(acc[i][j][2] + bib, 0.f),
                                                      fmaxf(acc[i][j][3] + bib, 0.f));
            *(__nv_bfloat162*)(Xs + r * XPAD + cc)       = h0;
            *(__nv_bfloat162*)(Xs + (r + 8) * XPAD + cc) = h1;
        }
    }
    stage_w(w2, Ws, tid);
    __syncthreads();

    // ---- GEMM2: tok += scale * (W2 @ h1 + b2) ----
    mm_tc(Ws, Xs, acc, lane, m0, nb);
#pragma unroll
    for (int i = 0; i < 4; i++) {
        int r = r0 + 16 * i;
        float ba = __ldg(b2 + r),     sa = __ldg(scale + r);
        float bb = __ldg(b2 + r + 8), sb = __ldg(scale + r + 8);
        float* rowa = tok + ((size_t)b * Cc + r) * Nn + n0;
        float* rowb = tok + ((size_t)b * Cc + r + 8) * Nn + n0;
#pragma unroll
        for (int j = 0; j < 4; j++) {
            int cc = cb + 8 * j;
            float2 t0 = *(float2*)(rowa + cc);
            float2 t1 = *(float2*)(rowb + cc);
            t0.x = fmaf(sa, acc[i][j][0] + ba, t0.x);
            t0.y = fmaf(sa, acc[i][j][1] + ba, t0.y);
            t1.x = fmaf(sb, acc[i][j][2] + bb, t1.x);
            t1.y = fmaf(sb, acc[i][j][3] + bb, t1.y);
            *(float2*)(rowa + cc) = t0;
            *(float2*)(rowb + cc) = t1;
        }
    }
}

// ---------------- launch ----------------
extern "C" void kernel_launch(void* const* d_in, const int* in_sizes, int n_in,
                              void* d_out, int out_size) {
    const float* tokens   = (const float*)d_in[0];
    const int*   cell_ind = (const int*)d_in[1];
    const float* occ      = (const float*)d_in[2];
    const float* cm_gamma = (const float*)d_in[3];
    const float* cm_beta  = (const float*)d_in[4];
    const float* cm_w1    = (const float*)d_in[5];
    const float* cm_b1    = (const float*)d_in[6];
    const float* cm_w2    = (const float*)d_in[7];
    const float* cm_b2    = (const float*)d_in[8];
    const float* cm_scale = (const float*)d_in[9];
    const float* sm_gamma = (const float*)d_in[10];
    const float* sm_beta  = (const float*)d_in[11];
    const float* sm_k1    = (const float*)d_in[12];
    const float* sm_b1    = (const float*)d_in[13];
    const float* sm_k2    = (const float*)d_in[14];
    const float* sm_b2    = (const float*)d_in[15];
    const float* sm_scale = (const float*)d_in[16];
    float* tok = (float*)d_out;

    void *pA, *pB, *pCnt, *pW, *pAff, *pSt, *pW1f, *pW2b, *pB1f;
    cudaGetSymbolAddress(&pA, g_gridA);
    cudaGetSymbolAddress(&pB, g_gridB);
    cudaGetSymbolAddress(&pCnt, g_counts);
    cudaGetSymbolAddress(&pW, g_weight);
    cudaGetSymbolAddress(&pAff, g_aff);
    cudaGetSymbolAddress(&pSt, g_stats);
    cudaGetSymbolAddress(&pW1f, g_w1f);
    cudaGetSymbolAddress(&pW2b, g_w2b);
    cudaGetSymbolAddress(&pB1f, g_b1f);
    __nv_bfloat16* gridA = (__nv_bfloat16*)pA;
    __nv_bfloat16* gridB = (__nv_bfloat16*)pB;
    float* counts = (float*)pCnt;
    float* wgt = (float*)pW;
    float* aff = (float*)pAff;
    float* stats = (float*)pSt;
    __nv_bfloat16* w1f = (__nv_bfloat16*)pW1f;
    __nv_bfloat16* w2b = (__nv_bfloat16*)pW2b;
    float* b1f = (float*)pB1f;

    const int smem_gemm = (256 * WPAD + 256 * XPAD) * sizeof(__nv_bfloat16);  // 204800
    cudaFuncSetAttribute(gemm_tc_kernel, cudaFuncAttributeMaxDynamicSharedMemorySize, smem_gemm);

    // working copy of tokens into d_out; zero stats accumulators
    cudaMemcpyAsync(tok, tokens, (size_t)Bc * Cc * Nn * sizeof(float), cudaMemcpyDeviceToDevice);
    cudaMemsetAsync(stats, 0, 2 * Cc * sizeof(float));

    // counts & weights (reused for all d)
    cudaMemsetAsync(counts, 0, (size_t)Bc * NGc * HWc * sizeof(float));
    count_kernel<<<(Bc * NGc * Nn) / 256, 256>>>(cell_ind, occ, counts);
    weight_kernel<<<(Bc * NGc * Nn) / 256, 256>>>(cell_ind, occ, counts, wgt);

    // all W2 -> bf16 once
    cvt_bf16_kernel<<<(Dd * Cc * Cc) / 256, 256>>>(cm_w2, w2b);

    dim3 tileGrid(Nn / 32, Cc / 32, Bc), tileBlk(32, 32);
    dim3 convGrid(Hh / 8, Ww / 64, Bc);
    dim3 statsGrid(Cc, Bc * 4);

    for (int d = 0; d < Dd; d++) {
        int g = d % NGc;
        // ---- spatial mixing ----
        stats_kernel<<<statsGrid, 256>>>(tok, stats);
        aff_kernel<<<1, 256>>>(stats, sm_gamma + d * Cc, sm_beta + d * Cc, aff);
        cudaMemsetAsync(gridA, 0, (size_t)Bc * HWc * Cc * sizeof(__nv_bfloat16));
        scatter_kernel<<<tileGrid, tileBlk>>>(tok, cell_ind, g, wgt, aff, gridA);
        dwconv2_kernel<<<convGrid, 256>>>(gridA, sm_k1 + (size_t)d * Cc * 9, sm_b1 + d * Cc,
                                          sm_k2 + (size_t)d * Cc * 9, sm_b2 + d * Cc, gridB);
        gather_kernel<<<tileGrid, tileBlk>>>(gridB, cell_ind, g, occ, sm_scale + d * Cc, tok);
        // ---- channel mixing ----
        stats_kernel<<<statsGrid, 256>>>(tok, stats);
        aff_kernel<<<1, 256>>>(stats, cm_gamma + d * Cc, cm_beta + d * Cc, aff);
        fold_kernel<<<Cc, 256>>>(cm_w1 + (size_t)d * Cc * Cc, cm_b1 + d * Cc, aff, w1f, b1f);
        gemm_tc_kernel<<<Bc * (Nn / GNT), 512, smem_gemm>>>(
            tok, w1f, b1f, w2b + (size_t)d * Cc * Cc, cm_b2 + d * Cc, cm_scale + d * Cc);
    }
}

// round 16
// speedup vs baseline: 1.1014x; 1.1014x over previous
#include <cuda_runtime.h>
#include <cuda_bf16.h>
#include <cstdint>
#include <cstddef>

#define Bc  2
#define Cc  256
#define Nn  32768
#define Dd  4
#define Hh  256
#define Ww  256
#define HWc 65536
#define NGc 3

// ---------------- device scratch (static, no allocs) ----------------
__device__ float g_gridA[(size_t)Bc * HWc * Cc];           // 134 MB fp32 (atomic target)
__device__ __nv_bfloat16 g_gridB[(size_t)Bc * HWc * Cc];   // 67 MB bf16 (conv output)
__device__ float g_counts[Bc * NGc * HWc];
__device__ float g_weight[Bc * NGc * Nn];
__device__ float g_aff[2 * Cc];                    // spatial affine a[c], bv[c]
__device__ float g_statsA[2 * Cc];                 // spatial-BN accumulators
__device__ float g_statsB[2 * Cc];                 // channel-BN accumulators
__device__ __nv_bfloat16 g_w1f[Cc * Cc];
__device__ __nv_bfloat16 g_w2b[Dd * Cc * Cc];
__device__ float g_b1f[Cc];

// ---------------- counts / weights ----------------
__global__ void count_kernel(const int* __restrict__ cell, const float* __restrict__ occ,
                             float* __restrict__ counts) {
    int i = blockIdx.x * 256 + threadIdx.x;
    int n = i % Nn;
    int bg = i / Nn;
    int b = bg / NGc;
    atomicAdd(&counts[(size_t)bg * HWc + cell[i]], occ[(size_t)b * Nn + n]);
}

__global__ void weight_kernel(const int* __restrict__ cell, const float* __restrict__ occ,
                              const float* __restrict__ counts, float* __restrict__ w) {
    int i = blockIdx.x * 256 + threadIdx.x;
    int n = i % Nn;
    int bg = i / Nn;
    int b = bg / NGc;
    float o = occ[(size_t)b * Nn + n];
    float cnt = counts[(size_t)bg * HWc + cell[i]] * o;
    w[i] = o / (cnt + 1e-6f);
}

// ------- BN stats: per-(c, b, quarter) partial sums -> global atomics -------
#define SCHUNK (Nn / 4)
__global__ void stats_kernel(const float* __restrict__ tok, float* __restrict__ stats) {
    int c = blockIdx.x;
    int bq = blockIdx.y;            // b * 4 + quarter
    int b = bq >> 2, qt = bq & 3;
    int t = threadIdx.x;
    float s = 0.f, s2 = 0.f;
    const float4* p = (const float4*)(tok + ((size_t)b * Cc + c) * Nn + qt * SCHUNK);
#pragma unroll 4
    for (int i = t; i < SCHUNK / 4; i += 256) {
        float4 v = p[i];
        s  += v.x + v.y + v.z + v.w;
        s2 += v.x * v.x + v.y * v.y + v.z * v.z + v.w * v.w;
    }
    __shared__ float sh0[256], sh1[256];
    sh0[t] = s; sh1[t] = s2;
    __syncthreads();
    for (int o = 128; o > 0; o >>= 1) {
        if (t < o) { sh0[t] += sh0[t + o]; sh1[t] += sh1[t + o]; }
        __syncthreads();
    }
    if (t == 0) {
        atomicAdd(&stats[c], sh0[0]);
        atomicAdd(&stats[Cc + c], sh1[0]);
    }
}

// ------- spatial stats -> affine; re-zero statsA AND statsB for this layer -------
__global__ void aff_kernel(float* __restrict__ statsA, float* __restrict__ statsB,
                           const float* __restrict__ gamma, const float* __restrict__ beta,
                           float* __restrict__ aff) {
    int c = threadIdx.x;
    const float inv = 1.0f / (float)(Bc * Nn);
    float m = statsA[c] * inv;
    float v = statsA[Cc + c] * inv - m * m;
    float a = gamma[c] * rsqrtf(v + 1e-5f);
    aff[c] = a;
    aff[Cc + c] = beta[c] - m * a;
    statsA[c] = 0.f;
    statsA[Cc + c] = 0.f;
    statsB[c] = 0.f;
    statsB[Cc + c] = 0.f;
}

// ---------------- scatter (BN folded inline, fp32 atomics — R10-proven) -------
__global__ void scatter_kernel(const float* __restrict__ tok, const int* __restrict__ cell_ind,
                               int g, const float* __restrict__ wgt, const float* __restrict__ aff,
                               float* __restrict__ grid) {
    int tx = threadIdx.x, ty = threadIdx.y;
    int n0 = blockIdx.x * 32, c0 = blockIdx.y * 32, b = blockIdx.z;
    __shared__ float s[32][33];
    __shared__ int   cs[32];
    __shared__ float ws[32];
    s[ty][tx] = tok[((size_t)b * Cc + c0 + ty) * Nn + n0 + tx];
    if (ty == 0) {
        cs[tx] = cell_ind[((size_t)b * NGc + g) * Nn + n0 + tx];
        ws[tx] = wgt[((size_t)b * NGc + g) * Nn + n0 + tx];
    }
    __syncthreads();
    int c = c0 + tx;
    float a = aff[c], bv = aff[Cc + c];
    float r = fmaf(a, s[tx][ty], bv);
    float contrib = ws[ty] * r;
    atomicAdd(&grid[((size_t)b * HWc + cs[ty]) * Cc + c], contrib);
}

// -------- fused depthwise 3x3 conv x2 (relu between), NHWC, f32 in / bf16 out ----
// y-tile: 8 output rows per block (12 input rows, 10 conv1 rows) -> 1.5x y-overread
__global__ void dwconv2_kernel(const float* __restrict__ in, const float* __restrict__ kk1,
                               const float* __restrict__ kb1, const float* __restrict__ kk2,
                               const float* __restrict__ kb2, __nv_bfloat16* __restrict__ out) {
    int c  = threadIdx.x;
    int y0 = blockIdx.x * 8;
    int x0 = blockIdx.y * 64;
    int b  = blockIdx.z;
    float ka[9], kb[9];
#pragma unroll
    for (int i = 0; i < 9; i++) { ka[i] = kk1[c * 9 + i]; kb[i] = kk2[c * 9 + i]; }
    float b1 = kb1[c], b2 = kb2[c];
    const float* base    = in  + (size_t)b * HWc * Cc + c;
    __nv_bfloat16* obase = out + (size_t)b * HWc * Cc + c;

    bool rin[12];
    size_t rofi[12];
#pragma unroll
    for (int r = 0; r < 12; r++) {
        int yr = y0 - 2 + r;
        rin[r] = (yr >= 0 && yr < Hh);
        rofi[r] = (size_t)(rin[r] ? yr : 0) * Ww * Cc;
    }
    bool rc1[10];
#pragma unroll
    for (int r = 0; r < 10; r++) {
        int yc = y0 - 1 + r;
        rc1[r] = (yc >= 0 && yc < Hh);
    }

    float i0[12], i1[12], i2[12], c10[10], c11[10], c12[10];
#pragma unroll
    for (int r = 0; r < 10; r++) { c10[r] = 0.f; c11[r] = 0.f; }

    {
        int x = x0 - 2;
        bool ok = (x >= 0 && x < Ww);
        size_t xi = (size_t)(ok ? x : 0) * Cc;
#pragma unroll
        for (int r = 0; r < 12; r++) i0[r] = (ok && rin[r]) ? base[rofi[r] + xi] : 0.f;
    }
    {
        int x = x0 - 1;
        bool ok = (x >= 0 && x < Ww);
        size_t xi = (size_t)(ok ? x : 0) * Cc;
#pragma unroll
        for (int r = 0; r < 12; r++) i1[r] = (ok && rin[r]) ? base[rofi[r] + xi] : 0.f;
    }

    for (int xc = x0 - 1; xc <= x0 + 64; xc++) {
        {
            int x = xc + 1;
            bool ok = (x >= 0 && x < Ww);
            size_t xi = (size_t)(ok ? x : 0) * Cc;
#pragma unroll
            for (int r = 0; r < 12; r++) i2[r] = (ok && rin[r]) ? base[rofi[r] + xi] : 0.f;
        }
        bool xok = (xc >= 0 && xc < Ww);
#pragma unroll
        for (int r = 0; r < 10; r++) {
            float a = b1;
            a = fmaf(ka[0], i0[r],     a);
            a = fmaf(ka[1], i1[r],     a);
            a = fmaf(ka[2], i2[r],     a);
            a = fmaf(ka[3], i0[r + 1], a);
            a = fmaf(ka[4], i1[r + 1], a);
            a = fmaf(ka[5], i2[r + 1], a);
            a = fmaf(ka[6], i0[r + 2], a);
            a = fmaf(ka[7], i1[r + 2], a);
            a = fmaf(ka[8], i2[r + 2], a);
            c12[r] = (xok && rc1[r]) ? fmaxf(a, 0.f) : 0.f;
        }
        if (xc >= x0 + 1) {
            int xo = xc - 1;
#pragma unroll
            for (int o = 0; o < 8; o++) {
                float a = b2;
                a = fmaf(kb[0], c10[o],     a);
                a = fmaf(kb[1], c11[o],     a);
                a = fmaf(kb[2], c12[o],     a);
                a = fmaf(kb[3], c10[o + 1], a);
                a = fmaf(kb[4], c11[o + 1], a);
                a = fmaf(kb[5], c12[o + 1], a);
                a = fmaf(kb[6], c10[o + 2], a);
                a = fmaf(kb[7], c11[o + 2], a);
                a = fmaf(kb[8], c12[o + 2], a);
                obase[((size_t)(y0 + o) * Ww + xo) * Cc] = __float2bfloat16(a);
            }
        }
#pragma unroll
        for (int r = 0; r < 12; r++) { i0[r] = i1[r]; i1[r] = i2[r]; }
#pragma unroll
        for (int r = 0; r < 10; r++) { c10[r] = c11[r]; c11[r] = c12[r]; }
    }
}

// ------- gather + residual; also zeroes gridA (dead after conv) for next scatter ----
__global__ void gather_kernel(const __nv_bfloat16* __restrict__ grid,
                              const int* __restrict__ cell_ind, int g,
                              const float* __restrict__ occ, const float* __restrict__ scale,
                              float* __restrict__ tok, float2* __restrict__ gridz) {
    int tx = threadIdx.x, ty = threadIdx.y;
    int n0 = blockIdx.x * 32, c0 = blockIdx.y * 32, b = blockIdx.z;
    __shared__ float s[32][33];
    __shared__ int   cs[32];
    __shared__ float os[32];
    if (ty == 0) {
        cs[tx] = cell_ind[((size_t)b * NGc + g) * Nn + n0 + tx];
        os[tx] = occ[(size_t)b * Nn + n0 + tx];
    }
    __syncthreads();
    float v = __bfloat162float(grid[((size_t)b * HWc + cs[ty]) * Cc + c0 + tx]) * os[ty];
    s[tx][ty] = v;
    __syncthreads();
    size_t o = ((size_t)b * Cc + c0 + ty) * Nn + n0 + tx;
    tok[o] = fmaf(scale[c0 + ty], s[ty][tx], tok[o]);
    // zero a 8 KB chunk of gridA (fp32): 16384 blocks x 1024 threads x 1 float2
    size_t lin = (size_t)blockIdx.x + 1024u * blockIdx.y + 8192u * blockIdx.z;
    gridz[lin * 1024 + ty * 32 + tx] = make_float2(0.f, 0.f);
}

// ------- fold BN affine into W1 (affine computed inline from channel stats) -------
__global__ void fold_kernel(const float* __restrict__ w1, const float* __restrict__ b1,
                            const float* __restrict__ statsB, const float* __restrict__ gamma,
                            const float* __restrict__ beta, __nv_bfloat16* __restrict__ w1f,
                            float* __restrict__ b1f) {
    int o = blockIdx.x, t = threadIdx.x;
    const float inv = 1.0f / (float)(Bc * Nn);
    float m = statsB[t] * inv;
    float vv = statsB[Cc + t] * inv - m * m;
    float a = gamma[t] * rsqrtf(vv + 1e-5f);
    float bv = beta[t] - m * a;
    float wv = w1[(size_t)o * Cc + t];
    w1f[(size_t)o * Cc + t] = __float2bfloat16(wv * a);
    float p = wv * bv;
    __shared__ float sh[256];
    sh[t] = p;
    __syncthreads();
    for (int s = 128; s > 0; s >>= 1) {
        if (t < s) sh[t] += sh[t + s];
        __syncthreads();
    }
    if (t == 0) b1f[o] = b1[o] + sh[0];
}

__global__ void cvt_bf16_kernel(const float* __restrict__ src, __nv_bfloat16* __restrict__ dst) {
    int i = blockIdx.x * 256 + threadIdx.x;
    dst[i] = __float2bfloat16(src[i]);
}

// ------- tensor-core fused double GEMM + residual: whole-W smem residency -------
#define GNT 128
#define XPAD 136   // 128 + 8 bf16 pad
#define WPAD 264   // 256 + 8 bf16 pad

__device__ __forceinline__ uint32_t smem_u32(const void* p) {
    return (uint32_t)__cvta_generic_to_shared(p);
}

#define MMA16816(ac, A, B)                                                        \
    asm volatile("mma.sync.aligned.m16n8k16.row.col.f32.bf16.bf16.f32 "           \
                 "{%0,%1,%2,%3},{%4,%5,%6,%7},{%8,%9},{%0,%1,%2,%3};"             \
                 : "+f"(ac[0]), "+f"(ac[1]), "+f"(ac[2]), "+f"(ac[3])             \
                 : "r"(A[0]), "r"(A[1]), "r"(A[2]), "r"(A[3]), "r"(B[0]), "r"(B[1]))

__device__ __forceinline__ void stage_w(const __nv_bfloat16* __restrict__ W,
                                        __nv_bfloat16* __restrict__ Ws, int tid) {
#pragma unroll
    for (int it = 0; it < 16; it++) {
        int f = it * 512 + tid;
        int row = f >> 5;
        int col8 = (f & 31) << 3;
        uint4 v = *(const uint4*)(W + (size_t)row * 256 + col8);
        *(uint4*)(Ws + row * WPAD + col8) = v;
    }
}

__device__ __forceinline__ void mm_tc(const __nv_bfloat16* __restrict__ Ws,
                                      const __nv_bfloat16* __restrict__ Bsm,
                                      float (&acc)[4][4][4], int lane, int m0, int nb) {
#pragma unroll
    for (int i = 0; i < 4; i++)
#pragma unroll
        for (int j = 0; j < 4; j++)
#pragma unroll
            for (int q = 0; q < 4; q++) acc[i][j][q] = 0.f;

#pragma unroll
    for (int ks = 0; ks < 16; ks++) {
        int k0 = ks * 16;
        uint32_t a[4][4];
#pragma unroll
        for (int i = 0; i < 4; i++) {
            const __nv_bfloat16* p =
                Ws + (m0 + 16 * i + (lane & 15)) * WPAD + k0 + ((lane >> 4) << 3);
            asm volatile("ldmatrix.sync.aligned.m8n8.x4.shared.b16 {%0,%1,%2,%3}, [%4];"
                         : "=r"(a[i][0]), "=r"(a[i][1]), "=r"(a[i][2]), "=r"(a[i][3])
                         : "r"(smem_u32(p)));
        }
        uint32_t bf[4][2];
#pragma unroll
        for (int jj = 0; jj < 2; jj++) {
            const __nv_bfloat16* q =
                Bsm + (k0 + (lane & 15)) * XPAD + nb + 16 * jj + ((lane >> 4) << 3);
            asm volatile("ldmatrix.sync.aligned.m8n8.x4.trans.shared.b16 {%0,%1,%2,%3}, [%4];"
                         : "=r"(bf[2 * jj][0]), "=r"(bf[2 * jj][1]),
                           "=r"(bf[2 * jj + 1][0]), "=r"(bf[2 * jj + 1][1])
                         : "r"(smem_u32(q)));
        }
#pragma unroll
        for (int i = 0; i < 4; i++)
#pragma unroll
            for (int j = 0; j < 4; j++) MMA16816(acc[i][j], a[i], bf[j]);
    }
}

__global__ void __launch_bounds__(512, 1)
gemm_tc_kernel(float* __restrict__ tok, const __nv_bfloat16* __restrict__ w1f,
               const float* __restrict__ b1f, const __nv_bfloat16* __restrict__ w2,
               const float* __restrict__ b2, const float* __restrict__ scale) {
    extern __shared__ __nv_bfloat16 sm[];
    __nv_bfloat16* Ws = sm;                       // 256 * 264
    __nv_bfloat16* Xs = sm + 256 * WPAD;          // 256 * 136 — also h1
    int tid = threadIdx.x;
    int b   = blockIdx.x >> 8;
    int n0  = (blockIdx.x & 255) << 7;

    stage_w(w1f, Ws, tid);
    const float* tb = tok + (size_t)b * Cc * Nn;
#pragma unroll
    for (int i = 0; i < 16; i++) {
        int idx = i * 512 + tid;
        int row = idx >> 5;
        int c4  = idx & 31;
        float4 v = *(const float4*)(tb + (size_t)row * Nn + n0 + c4 * 4);
        __nv_bfloat162 p0 = __floats2bfloat162_rn(v.x, v.y);
        __nv_bfloat162 p1 = __floats2bfloat162_rn(v.z, v.w);
        uint2 pk;
        pk.x = *(uint32_t*)&p0;
        pk.y = *(uint32_t*)&p1;
        *(uint2*)(Xs + row * XPAD + c4 * 4) = pk;
    }
    __syncthreads();

    int lane = tid & 31, warp = tid >> 5;
    int m0 = (warp >> 2) * 64;
    int nb = (warp & 3) * 32;
    int r0 = m0 + (lane >> 2);
    int cb = nb + 2 * (lane & 3);

    float acc[4][4][4];

    // ---- GEMM1: h1 = relu(W1f @ x + b1f) ----
    mm_tc(Ws, Xs, acc, lane, m0, nb);
    __syncthreads();
#pragma unroll
    for (int i = 0; i < 4; i++) {
        int r = r0 + 16 * i;
        float bia = __ldg(b1f + r);
        float bib = __ldg(b1f + r + 8);
#pragma unroll
        for (int j = 0; j < 4; j++) {
            int cc = cb + 8 * j;
            __nv_bfloat162 h0 = __floats2bfloat162_rn(fmaxf(acc[i][j][0] + bia, 0.f),
                                                      fmaxf(acc[i][j][1] + bia, 0.f));
            __nv_bfloat162 h1 = __floats2bfloat162_rn(fmaxf(acc[i][j][2] + bib, 0.f),
                                                      fmaxf(acc[i][j][3] + bib, 0.f));
            *(__nv_bfloat162*)(Xs + r * XPAD + cc)       = h0;
            *(__nv_bfloat162*)(Xs + (r + 8) * XPAD + cc) = h1;
        }
    }
    stage_w(w2, Ws, tid);
    __syncthreads();

    // ---- GEMM2: tok += scale * (W2 @ h1 + b2) ----
    mm_tc(Ws, Xs, acc, lane, m0, nb);
#pragma unroll
    for (int i = 0; i < 4; i++) {
        int r = r0 + 16 * i;
        float ba = __ldg(b2 + r),     sa = __ldg(scale + r);
        float bb = __ldg(b2 + r + 8), sb = __ldg(scale + r + 8);
        float* rowa = tok + ((size_t)b * Cc + r) * Nn + n0;
        float* rowb = tok + ((size_t)b * Cc + r + 8) * Nn + n0;
#pragma unroll
        for (int j = 0; j < 4; j++) {
            int cc = cb + 8 * j;
            float2 t0 = *(float2*)(rowa + cc);
            float2 t1 = *(float2*)(rowb + cc);
            t0.x = fmaf(sa, acc[i][j][0] + ba, t0.x);
            t0.y = fmaf(sa, acc[i][j][1] + ba, t0.y);
            t1.x = fmaf(sb, acc[i][j][2] + bb, t1.x);
            t1.y = fmaf(sb, acc[i][j][3] + bb, t1.y);
            *(float2*)(rowa + cc) = t0;
            *(float2*)(rowb + cc) = t1;
        }
    }
}

// ---------------- launch ----------------
extern "C" void kernel_launch(void* const* d_in, const int* in_sizes, int n_in,
                              void* d_out, int out_size) {
    const float* tokens   = (const float*)d_in[0];
    const int*   cell_ind = (const int*)d_in[1];
    const float* occ      = (const float*)d_in[2];
    const float* cm_gamma = (const float*)d_in[3];
    const float* cm_beta  = (const float*)d_in[4];
    const float* cm_w1    = (const float*)d_in[5];
    const float* cm_b1    = (const float*)d_in[6];
    const float* cm_w2    = (const float*)d_in[7];
    const float* cm_b2    = (const float*)d_in[8];
    const float* cm_scale = (const float*)d_in[9];
    const float* sm_gamma = (const float*)d_in[10];
    const float* sm_beta  = (const float*)d_in[11];
    const float* sm_k1    = (const float*)d_in[12];
    const float* sm_b1    = (const float*)d_in[13];
    const float* sm_k2    = (const float*)d_in[14];
    const float* sm_b2    = (const float*)d_in[15];
    const float* sm_scale = (const float*)d_in[16];
    float* tok = (float*)d_out;

    void *pA, *pB, *pCnt, *pW, *pAff, *pStA, *pStB, *pW1f, *pW2b, *pB1f;
    cudaGetSymbolAddress(&pA, g_gridA);
    cudaGetSymbolAddress(&pB, g_gridB);
    cudaGetSymbolAddress(&pCnt, g_counts);
    cudaGetSymbolAddress(&pW, g_weight);
    cudaGetSymbolAddress(&pAff, g_aff);
    cudaGetSymbolAddress(&pStA, g_statsA);
    cudaGetSymbolAddress(&pStB, g_statsB);
    cudaGetSymbolAddress(&pW1f, g_w1f);
    cudaGetSymbolAddress(&pW2b, g_w2b);
    cudaGetSymbolAddress(&pB1f, g_b1f);
    float* gridA = (float*)pA;
    __nv_bfloat16* gridB = (__nv_bfloat16*)pB;
    float* counts = (float*)pCnt;
    float* wgt = (float*)pW;
    float* aff = (float*)pAff;
    float* statsA = (float*)pStA;
    float* statsB = (float*)pStB;
    __nv_bfloat16* w1f = (__nv_bfloat16*)pW1f;
    __nv_bfloat16* w2b = (__nv_bfloat16*)pW2b;
    float* b1f = (float*)pB1f;

    const int smem_gemm = (256 * WPAD + 256 * XPAD) * sizeof(__nv_bfloat16);  // 204800
    cudaFuncSetAttribute(gemm_tc_kernel, cudaFuncAttributeMaxDynamicSharedMemorySize, smem_gemm);

    // working copy of tokens into d_out; zero stats accumulators; zero gridA ONCE
    cudaMemcpyAsync(tok, tokens, (size_t)Bc * Cc * Nn * sizeof(float), cudaMemcpyDeviceToDevice);
    cudaMemsetAsync(statsA, 0, 2 * Cc * sizeof(float));
    cudaMemsetAsync(statsB, 0, 2 * Cc * sizeof(float));
    cudaMemsetAsync(gridA, 0, (size_t)Bc * HWc * Cc * sizeof(float));

    // counts & weights (reused for all d)
    cudaMemsetAsync(counts, 0, (size_t)Bc * NGc * HWc * sizeof(float));
    count_kernel<<<(Bc * NGc * Nn) / 256, 256>>>(cell_ind, occ, counts);
    weight_kernel<<<(Bc * NGc * Nn) / 256, 256>>>(cell_ind, occ, counts, wgt);

    // all W2 -> bf16 once
    cvt_bf16_kernel<<<(Dd * Cc * Cc) / 256, 256>>>(cm_w2, w2b);

    dim3 tileGrid(Nn / 32, Cc / 32, Bc), tileBlk(32, 32);
    dim3 convGrid(Hh / 8, Ww / 64, Bc);
    dim3 statsGrid(Cc, Bc * 4);

    for (int d = 0; d < Dd; d++) {
        int g = d % NGc;
        // ---- spatial mixing ----
        stats_kernel<<<statsGrid, 256>>>(tok, statsA);
        aff_kernel<<<1, 256>>>(statsA, statsB, sm_gamma + d * Cc, sm_beta + d * Cc, aff);
        scatter_kernel<<<tileGrid, tileBlk>>>(tok, cell_ind, g, wgt, aff, gridA);
        dwconv2_kernel<<<convGrid, 256>>>(gridA, sm_k1 + (size_t)d * Cc * 9, sm_b1 + d * Cc,
                                          sm_k2 + (size_t)d * Cc * 9, sm_b2 + d * Cc, gridB);
        gather_kernel<<<tileGrid, tileBlk>>>(gridB, cell_ind, g, occ, sm_scale + d * Cc, tok,
                                             (float2*)gridA);
        // ---- channel mixing ----
        stats_kernel<<<statsGrid, 256>>>(tok, statsB);
        fold_kernel<<<Cc, 256>>>(cm_w1 + (size_t)d * Cc * Cc, cm_b1 + d * Cc, statsB,
                                 cm_gamma + d * Cc, cm_beta + d * Cc, w1f, b1f);
        gemm_tc_kernel<<<Bc * (Nn / GNT), 512, smem_gemm>>>(
            tok, w1f, b1f, w2b + (size_t)d * Cc * Cc, cm_b2 + d * Cc, cm_scale + d * Cc);
    }
}